// round 15
// baseline (speedup 1.0000x reference)
#include <cuda_runtime.h>
#include <cuda_fp16.h>
#include <math.h>
#include <stdint.h>

#define BB 2
#define SS 2048
#define HQN 32
#define HKV 8
#define DD 128
#define SCALING 0.08838834764831845f
#define LOG2E 1.4426950408889634f

// ---------------- device scratch ----------------
__device__ __half g_kg[(size_t)BB * HKV * SS * DD];  // K' [b][h][s][d] (scale folded)
__device__ __half g_vg[(size_t)BB * HKV * SS * DD];  // V' [b][h][s][d] (scale folded)

// ---------------- prep: e4m3 qd (bit-exact) -> fp4 dequant, scale folded ----------------
__device__ __forceinline__ float e4m3_qd(float x) {
    uint32_t u = __float_as_uint(x);
    uint32_t au = u & 0x7FFFFFFFu;
    float ax = __uint_as_float(au);
    uint32_t lsb = (au >> 20) & 1u;
    uint32_t r = au + 0x7FFFFu + lsb;
    float fn = fminf(__uint_as_float(r & 0xFFF00000u), 448.0f);
    float fs = rintf(ax * 512.0f) * (1.0f / 512.0f);
    float q = (ax < 0.015625f) ? fs : fn;
    return copysignf(q, x);
}

__global__ void prep_kernel(const float* __restrict__ ksrc, const float* __restrict__ vsrc) {
    int which = blockIdx.y;
    const float* __restrict__ src = which ? vsrc : ksrc;
    int gw = (blockIdx.x * blockDim.x + threadIdx.x) >> 5;
    if (gw >= BB * SS * HKV) return;
    int lane = threadIdx.x & 31;
    int h = gw % HKV;
    int t = gw / HKV;
    int s = t % SS;
    int b = t / SS;

    const float4* p = (const float4*)(src + ((size_t)(b * SS + s) * HKV + h) * DD);
    float4 xv = p[lane];
    float qq[4];
    qq[0] = e4m3_qd(xv.x); qq[1] = e4m3_qd(xv.y);
    qq[2] = e4m3_qd(xv.z); qq[3] = e4m3_qd(xv.w);

    float am = fmaxf(fmaxf(fabsf(qq[0]), fabsf(qq[1])), fmaxf(fabsf(qq[2]), fabsf(qq[3])));
    #pragma unroll
    for (int o = 16; o >= 1; o >>= 1)
        am = fmaxf(am, __shfl_xor_sync(0xffffffffu, am, o));
    float scale = fmaxf(__fdiv_rn(am, 6.0f), 1e-12f);

    float rr[4];
    #pragma unroll
    for (int u = 0; u < 4; ++u) {
        float xn = __fdiv_rn(qq[u], scale);
        float axn = fabsf(xn);
        float g = axn <= 0.25f ? 0.0f :
                  axn <= 0.75f ? 0.5f :
                  axn <= 1.25f ? 1.0f :
                  axn <= 1.75f ? 1.5f :
                  axn <= 2.5f  ? 2.0f :
                  axn <= 3.5f  ? 3.0f :
                  axn <= 5.0f  ? 4.0f : 6.0f;
        float sg = xn > 0.0f ? 1.0f : (xn < 0.0f ? -1.0f : 0.0f);
        rr[u] = sg * g * scale;
    }

    size_t bh = (size_t)(b * HKV + h);
    __half* dst = (which ? g_vg : g_kg) + (bh * SS + s) * DD + lane * 4;
    dst[0] = __float2half_rn(rr[0]); dst[1] = __float2half_rn(rr[1]);
    dst[2] = __float2half_rn(rr[2]); dst[3] = __float2half_rn(rr[3]);
}

// ---------------- mma.sync helpers ----------------
__device__ __forceinline__ uint32_t smem_u32(const void* p) {
    uint32_t a;
    asm("{ .reg .u64 t; cvta.to.shared.u64 t, %1; cvt.u32.u64 %0, t; }" : "=r"(a) : "l"(p));
    return a;
}

#define MMA_F16(c, a0, a1, a2, a3, b0, b1)                                      \
    asm volatile("mma.sync.aligned.m16n8k16.row.col.f32.f16.f16.f32 "           \
        "{%0,%1,%2,%3}, {%4,%5,%6,%7}, {%8,%9}, {%0,%1,%2,%3};"                 \
        : "+f"((c)[0]), "+f"((c)[1]), "+f"((c)[2]), "+f"((c)[3])                \
        : "r"(a0), "r"(a1), "r"(a2), "r"(a3), "r"(b0), "r"(b1))

#define LDSM4(r, a)                                                             \
    asm volatile("ldmatrix.sync.aligned.m8n8.x4.shared.b16 {%0,%1,%2,%3}, [%4];" \
        : "=r"((r)[0]), "=r"((r)[1]), "=r"((r)[2]), "=r"((r)[3]) : "r"(a))

#define LDSM4T(r, a)                                                            \
    asm volatile("ldmatrix.sync.aligned.m8n8.x4.trans.shared.b16 {%0,%1,%2,%3}, [%4];" \
        : "=r"((r)[0]), "=r"((r)[1]), "=r"((r)[2]), "=r"((r)[3]) : "r"(a))

#define CP16(dst, src) asm volatile("cp.async.cg.shared.global [%0], [%1], 16;" :: "r"(dst), "l"(src))
#define CPCOMMIT()     asm volatile("cp.async.commit_group;" ::: "memory")
#define CPWAIT1()      asm volatile("cp.async.wait_group 1;" ::: "memory")
#define BARPAIR(id)    asm volatile("bar.sync %0, 64;" :: "r"(id) : "memory")

__device__ __forceinline__ uint32_t pack_f16(float a, float b) {
    __half2 h = __floats2half2_rn(a, b);
    return *reinterpret_cast<uint32_t*>(&h);
}
__device__ __forceinline__ uint32_t ex2_f16x2(uint32_t a) {
    uint32_t r;
    asm("ex2.approx.f16x2 %0, %1;" : "=r"(r) : "r"(a));
    return r;
}

#define ONES2 0x3C003C00u  // half2(1.0, 1.0)

// K/V pitch: 136 halfs (272 B); P pitch: 72 halfs (144 B) -> both conflict-free ldmatrix.
#define PITCH 136
#define PPITCH 72
#define OFF_K0 0
#define OFF_K1 (64 * PITCH)
#define OFF_V0 (2 * 64 * PITCH)
#define OFF_V1 (3 * 64 * PITCH)
#define OFF_P  (4 * 64 * PITCH)
#define SMEM_HALFS (4 * 64 * PITCH + 64 * PPITCH)
#define SMEM_BYTES (SMEM_HALFS * 2)          // ~78.8 KB -> 2 CTAs/SM, 512 thr/SM

// ---------------- flash attention (8 warps: n-split GEMM1, D-split GEMM2) ----------------
__global__ __launch_bounds__(256, 2)
void attn_kernel(const float* __restrict__ q, float* __restrict__ out) {
    extern __shared__ __align__(16) __half smem[];

    const uint32_t sb = smem_u32(smem);
    int tid = threadIdx.x;
    int wid = tid >> 5;
    int r = wid & 3;               // row-group (16 rows)
    int h = wid >> 2;              // 0: n-half/D-half low, 1: high
    int lane = tid & 31;
    int lrow = lane & 15;
    int lcol = (lane >> 4) << 3;
    int qr = lane >> 2;
    int qc = (lane & 3) << 1;

    int idx = blockIdx.x;
    int bh = idx & 63;
    int mt = 31 - (idx >> 6);      // heavy tiles first
    int b = bh >> 5, hq = bh & 31, hkv = hq >> 2;
    int m0 = mt * 64;

    const __half* kgb = g_kg + (size_t)(b * HKV + hkv) * SS * DD;
    const __half* vgb = g_vg + (size_t)(b * HKV + hkv) * SS * DD;

    int srow = tid >> 4, sch = tid & 15;   // staging: 16 rows per pass, 4 passes
    const uint32_t koff[2] = {sb + (OFF_K0 + srow * PITCH + sch * 8) * 2,
                              sb + (OFF_K1 + srow * PITCH + sch * 8) * 2};
    const uint32_t voff[2] = {sb + (OFF_V0 + srow * PITCH + sch * 8) * 2,
                              sb + (OFF_V1 + srow * PITCH + sch * 8) * 2};

    auto stage = [&](int t, int bf) {
        int n0 = t * 64;
        const __half* kp = kgb + (size_t)(n0 + srow) * DD + sch * 8;
        const __half* vp = vgb + (size_t)(n0 + srow) * DD + sch * 8;
        #pragma unroll
        for (int j = 0; j < 4; ++j) {
            CP16(koff[bf] + j * 16 * PITCH * 2, kp + (size_t)j * 16 * DD);
            CP16(voff[bf] + j * 16 * PITCH * 2, vp + (size_t)j * 16 * DD);
        }
    };

    // ---- stage Q (pre-scaled by SCALING*LOG2E) through K0, hoist, free ----
    {
        int c = tid & 31, r8 = tid >> 5;
        const float* qb = q + ((size_t)(b * SS + m0) * HQN + hq) * DD;
        const float qs = SCALING * LOG2E;
        #pragma unroll
        for (int j = 0; j < 8; ++j) {
            int m = j * 8 + r8;
            float4 v = *(const float4*)(qb + (size_t)m * HQN * DD + c * 4);
            uint32_t* ph = (uint32_t*)(smem + OFF_K0 + m * PITCH + c * 4);
            ph[0] = pack_f16(v.x * qs, v.y * qs);
            ph[1] = pack_f16(v.z * qs, v.w * qs);
        }
    }
    __syncthreads();
    uint32_t qf[8][4];
    {
        const uint32_t q_base = sb + (OFF_K0 + (r * 16 + lrow) * PITCH + lcol) * 2;
        #pragma unroll
        for (int kc = 0; kc < 8; ++kc) LDSM4(qf[kc], q_base + kc * 32);
    }
    __syncthreads();  // all Q fragment reads done before K0 is overwritten

    stage(0, 0);
    CPCOMMIT();

    const uint32_t k_base[2] = {sb + (OFF_K0 + (h * 32 + lrow) * PITCH + lcol) * 2,
                                sb + (OFF_K1 + (h * 32 + lrow) * PITCH + lcol) * 2};
    const uint32_t v_base[2] = {sb + (OFF_V0 + lrow * PITCH + h * 64 + lcol) * 2,
                                sb + (OFF_V1 + lrow * PITCH + h * 64 + lcol) * 2};
    const uint32_t p_rbase = sb + (OFF_P + (r * 16 + lrow) * PPITCH + lcol) * 2;
    const uint32_t p_w0 = sb + (OFF_P + (r * 16 + qr) * PPITCH + 32 * h + qc) * 2;
    const uint32_t p_w1 = p_w0 + 8 * PPITCH * 2;

    float oacc[8][4];
    #pragma unroll
    for (int i = 0; i < 8; ++i)
        #pragma unroll
        for (int j = 0; j < 4; ++j) oacc[i][j] = 0.0f;
    float ls[4] = {0.0f, 0.0f, 0.0f, 0.0f};

    int rg0 = m0 + r * 16 + qr;
    int rg1 = rg0 + 8;

    int ntiles = mt + 1;
    for (int t = 0; t < ntiles; ++t) {
        int bf = t & 1;
        if (t + 1 < ntiles) stage(t + 1, bf ^ 1);
        CPCOMMIT();
        CPWAIT1();
        __syncthreads();

        int n0 = t * 64;
        bool diag = (t == ntiles - 1);

        // ---- GEMM1: S[16 x 32] (n-half h) = Q' * K'^T ----
        float sacc[4][4];
        #pragma unroll
        for (int i = 0; i < 4; ++i)
            #pragma unroll
            for (int j = 0; j < 4; ++j) sacc[i][j] = 0.0f;

        #pragma unroll
        for (int kc = 0; kc < 8; ++kc) {
            #pragma unroll
            for (int nb = 0; nb < 2; ++nb) {
                uint32_t kb[4];
                LDSM4(kb, k_base[bf] + nb * 16 * (PITCH * 2) + kc * 32);
                MMA_F16(sacc[2 * nb],     qf[kc][0], qf[kc][1], qf[kc][2], qf[kc][3], kb[0], kb[2]);
                MMA_F16(sacc[2 * nb + 1], qf[kc][0], qf[kc][1], qf[kc][2], qf[kc][3], kb[1], kb[3]);
            }
        }

        // ---- softmax (half-n) + write P half to smem ----
        #pragma unroll
        for (int j = 0; j < 4; ++j) {
            int cg = n0 + 32 * h + j * 8 + qc;
            float t00 = sacc[j][0];
            float t01 = sacc[j][1];
            float t10 = sacc[j][2];
            float t11 = sacc[j][3];
            if (diag) {
                t00 = (cg     > rg0) ? -1e4f : t00;
                t01 = (cg + 1 > rg0) ? -1e4f : t01;
                t10 = (cg     > rg1) ? -1e4f : t10;
                t11 = (cg + 1 > rg1) ? -1e4f : t11;
            }
            uint32_t e0 = ex2_f16x2(pack_f16(t00, t01));
            uint32_t e1 = ex2_f16x2(pack_f16(t10, t11));
            asm volatile("st.shared.b32 [%0], %1;" :: "r"(p_w0 + j * 16), "r"(e0) : "memory");
            asm volatile("st.shared.b32 [%0], %1;" :: "r"(p_w1 + j * 16), "r"(e1) : "memory");
        }
        BARPAIR(r + 1);  // pair (r,0)/(r,1) exchange P halves

        // ---- load full P as A-fragments; row sums via ones-MMA ----
        uint32_t pf[4][4];
        #pragma unroll
        for (int kt = 0; kt < 4; ++kt) LDSM4(pf[kt], p_rbase + kt * 32);
        #pragma unroll
        for (int kt = 0; kt < 4; ++kt)
            MMA_F16(ls, pf[kt][0], pf[kt][1], pf[kt][2], pf[kt][3], ONES2, ONES2);

        // ---- GEMM2: O[16 x 64-half] += P * V' ----
        #pragma unroll
        for (int kt = 0; kt < 4; ++kt) {
            #pragma unroll
            for (int db = 0; db < 4; ++db) {
                uint32_t vb[4];
                LDSM4T(vb, v_base[bf] + kt * 16 * (PITCH * 2) + db * 32);
                MMA_F16(oacc[2 * db],     pf[kt][0], pf[kt][1], pf[kt][2], pf[kt][3], vb[0], vb[1]);
                MMA_F16(oacc[2 * db + 1], pf[kt][0], pf[kt][1], pf[kt][2], pf[kt][3], vb[2], vb[3]);
            }
        }
        __syncthreads();  // all reads done before buffers are re-staged / P rewritten
    }

    // ---- epilogue: ls[0]/ls[2] are full row sums ----
    float inv0 = 1.0f / ls[0], inv1 = 1.0f / ls[2];

    float* o0 = out + ((size_t)(b * SS + rg0) * HQN + hq) * DD + h * 64;
    float* o1 = out + ((size_t)(b * SS + rg1) * HQN + hq) * DD + h * 64;
    #pragma unroll
    for (int dt = 0; dt < 8; ++dt) {
        int d = dt * 8 + qc;
        *(float2*)(o0 + d) = make_float2(oacc[dt][0] * inv0, oacc[dt][1] * inv0);
        *(float2*)(o1 + d) = make_float2(oacc[dt][2] * inv1, oacc[dt][3] * inv1);
    }
}

extern "C" void kernel_launch(void* const* d_in, const int* in_sizes, int n_in,
                              void* d_out, int out_size) {
    (void)in_sizes; (void)n_in; (void)out_size;
    const float* q = (const float*)d_in[0];
    const float* k = (const float*)d_in[1];
    const float* v = (const float*)d_in[2];
    float* out = (float*)d_out;

    cudaFuncSetAttribute(attn_kernel, cudaFuncAttributeMaxDynamicSharedMemorySize,
                         SMEM_BYTES);

    int prep_rows = BB * SS * HKV;
    dim3 pgrid((prep_rows * 32 + 255) / 256, 2);
    prep_kernel<<<pgrid, 256>>>(k, v);

    attn_kernel<<<(SS / 64) * BB * HQN, 256, SMEM_BYTES>>>(q, out);
}

// round 16
// speedup vs baseline: 1.0808x; 1.0808x over previous
#include <cuda_runtime.h>
#include <cuda_fp16.h>
#include <math.h>
#include <stdint.h>

#define BB 2
#define SS 2048
#define HQN 32
#define HKV 8
#define DD 128
#define SCALING 0.08838834764831845f
#define LOG2E 1.4426950408889634f

// ---------------- device scratch ----------------
__device__ __half g_kg[(size_t)BB * HKV * SS * DD];  // K' [b][h][s][d] (scale folded)
__device__ __half g_vg[(size_t)BB * HKV * SS * DD];  // V' [b][h][s][d] (scale folded)

// ---------------- prep: e4m3 qd (bit-exact) -> fp4 dequant, scale folded ----------------
__device__ __forceinline__ float e4m3_qd(float x) {
    uint32_t u = __float_as_uint(x);
    uint32_t au = u & 0x7FFFFFFFu;
    float ax = __uint_as_float(au);
    uint32_t lsb = (au >> 20) & 1u;
    uint32_t r = au + 0x7FFFFu + lsb;
    float fn = fminf(__uint_as_float(r & 0xFFF00000u), 448.0f);
    float fs = rintf(ax * 512.0f) * (1.0f / 512.0f);
    float q = (ax < 0.015625f) ? fs : fn;
    return copysignf(q, x);
}

__global__ void prep_kernel(const float* __restrict__ ksrc, const float* __restrict__ vsrc) {
    int which = blockIdx.y;
    const float* __restrict__ src = which ? vsrc : ksrc;
    int gw = (blockIdx.x * blockDim.x + threadIdx.x) >> 5;
    if (gw >= BB * SS * HKV) return;
    int lane = threadIdx.x & 31;
    int h = gw % HKV;
    int t = gw / HKV;
    int s = t % SS;
    int b = t / SS;

    const float4* p = (const float4*)(src + ((size_t)(b * SS + s) * HKV + h) * DD);
    float4 xv = p[lane];
    float qq[4];
    qq[0] = e4m3_qd(xv.x); qq[1] = e4m3_qd(xv.y);
    qq[2] = e4m3_qd(xv.z); qq[3] = e4m3_qd(xv.w);

    float am = fmaxf(fmaxf(fabsf(qq[0]), fabsf(qq[1])), fmaxf(fabsf(qq[2]), fabsf(qq[3])));
    #pragma unroll
    for (int o = 16; o >= 1; o >>= 1)
        am = fmaxf(am, __shfl_xor_sync(0xffffffffu, am, o));
    float scale = fmaxf(__fdiv_rn(am, 6.0f), 1e-12f);

    float rr[4];
    #pragma unroll
    for (int u = 0; u < 4; ++u) {
        float xn = __fdiv_rn(qq[u], scale);
        float axn = fabsf(xn);
        float g = axn <= 0.25f ? 0.0f :
                  axn <= 0.75f ? 0.5f :
                  axn <= 1.25f ? 1.0f :
                  axn <= 1.75f ? 1.5f :
                  axn <= 2.5f  ? 2.0f :
                  axn <= 3.5f  ? 3.0f :
                  axn <= 5.0f  ? 4.0f : 6.0f;
        float sg = xn > 0.0f ? 1.0f : (xn < 0.0f ? -1.0f : 0.0f);
        rr[u] = sg * g * scale;
    }

    size_t bh = (size_t)(b * HKV + h);
    __half* dst = (which ? g_vg : g_kg) + (bh * SS + s) * DD + lane * 4;
    dst[0] = __float2half_rn(rr[0]); dst[1] = __float2half_rn(rr[1]);
    dst[2] = __float2half_rn(rr[2]); dst[3] = __float2half_rn(rr[3]);
}

// ---------------- mma.sync helpers ----------------
__device__ __forceinline__ uint32_t smem_u32(const void* p) {
    uint32_t a;
    asm("{ .reg .u64 t; cvta.to.shared.u64 t, %1; cvt.u32.u64 %0, t; }" : "=r"(a) : "l"(p));
    return a;
}

#define MMA_F16(c, a0, a1, a2, a3, b0, b1)                                      \
    asm volatile("mma.sync.aligned.m16n8k16.row.col.f32.f16.f16.f32 "           \
        "{%0,%1,%2,%3}, {%4,%5,%6,%7}, {%8,%9}, {%0,%1,%2,%3};"                 \
        : "+f"((c)[0]), "+f"((c)[1]), "+f"((c)[2]), "+f"((c)[3])                \
        : "r"(a0), "r"(a1), "r"(a2), "r"(a3), "r"(b0), "r"(b1))

#define LDSM4(r, a)                                                             \
    asm volatile("ldmatrix.sync.aligned.m8n8.x4.shared.b16 {%0,%1,%2,%3}, [%4];" \
        : "=r"((r)[0]), "=r"((r)[1]), "=r"((r)[2]), "=r"((r)[3]) : "r"(a))

#define LDSM4T(r, a)                                                            \
    asm volatile("ldmatrix.sync.aligned.m8n8.x4.trans.shared.b16 {%0,%1,%2,%3}, [%4];" \
        : "=r"((r)[0]), "=r"((r)[1]), "=r"((r)[2]), "=r"((r)[3]) : "r"(a))

#define CP16(dst, src) asm volatile("cp.async.cg.shared.global [%0], [%1], 16;" :: "r"(dst), "l"(src))
#define CPCOMMIT()     asm volatile("cp.async.commit_group;" ::: "memory")
#define CPWAIT0()      asm volatile("cp.async.wait_group 0;" ::: "memory")

__device__ __forceinline__ uint32_t pack_f16(float a, float b) {
    __half2 h = __floats2half2_rn(a, b);
    return *reinterpret_cast<uint32_t*>(&h);
}
__device__ __forceinline__ uint32_t ex2_f16x2(uint32_t a) {
    uint32_t r;
    asm("ex2.approx.f16x2 %0, %1;" : "=r"(r) : "r"(a));
    return r;
}

#define ONES2 0x3C003C00u  // half2(1.0, 1.0)

// smem pitch: 136 halfs (272 B) per 128-elem row -> conflict-free ldmatrix.
#define PITCH 136
#define OFF_K0 0
#define OFF_K1 (64 * PITCH)
#define OFF_V0 (2 * 64 * PITCH)
#define OFF_V1 (3 * 64 * PITCH)
#define SMEM_HALFS (4 * 64 * PITCH)
#define SMEM_BYTES (SMEM_HALFS * 2)          // ~69.6 KB -> 3 CTAs/SM

// ---------------- flash attention (fp16 mma, single-sync pipeline) ----------------
__global__ __launch_bounds__(128, 3)
void attn_kernel(const float* __restrict__ q, float* __restrict__ out) {
    extern __shared__ __align__(16) __half smem[];

    const uint32_t sb = smem_u32(smem);
    int tid = threadIdx.x;
    int wid = tid >> 5;
    int lane = tid & 31;
    int lrow = lane & 15;
    int lcol = (lane >> 4) << 3;
    int qr = lane >> 2;
    int qc = (lane & 3) << 1;

    int idx = blockIdx.x;
    int bh = idx & 63;
    int mt = 31 - (idx >> 6);      // heavy tiles first
    int b = bh >> 5, hq = bh & 31, hkv = hq >> 2;
    int m0 = mt * 64;

    const __half* kgb = g_kg + (size_t)(b * HKV + hkv) * SS * DD;
    const __half* vgb = g_vg + (size_t)(b * HKV + hkv) * SS * DD;

    int srow = tid >> 4, sch = tid & 15;     // staging: 8 rows per pass
    const uint32_t koff[2] = {sb + (OFF_K0 + srow * PITCH + sch * 8) * 2,
                              sb + (OFF_K1 + srow * PITCH + sch * 8) * 2};
    const uint32_t voff[2] = {sb + (OFF_V0 + srow * PITCH + sch * 8) * 2,
                              sb + (OFF_V1 + srow * PITCH + sch * 8) * 2};

    auto stage = [&](int t, int bf) {
        int n0 = t * 64;
        const __half* kp = kgb + (size_t)(n0 + srow) * DD + sch * 8;
        const __half* vp = vgb + (size_t)(n0 + srow) * DD + sch * 8;
        #pragma unroll
        for (int j = 0; j < 8; ++j) {
            CP16(koff[bf] + j * 8 * PITCH * 2, kp + (size_t)j * 8 * DD);
            CP16(voff[bf] + j * 8 * PITCH * 2, vp + (size_t)j * 8 * DD);
        }
    };

    // ---- stage Q (pre-scaled by SCALING*LOG2E) through K0, hoist, free ----
    {
        int c = tid & 31, r4 = tid >> 5;
        const float* qb = q + ((size_t)(b * SS + m0) * HQN + hq) * DD;
        const float qs = SCALING * LOG2E;
        #pragma unroll
        for (int j = 0; j < 16; ++j) {
            int m = j * 4 + r4;
            float4 v = *(const float4*)(qb + (size_t)m * HQN * DD + c * 4);
            uint32_t* ph = (uint32_t*)(smem + OFF_K0 + m * PITCH + c * 4);
            ph[0] = pack_f16(v.x * qs, v.y * qs);
            ph[1] = pack_f16(v.z * qs, v.w * qs);
        }
    }
    __syncthreads();
    uint32_t qf[8][4];
    {
        const uint32_t q_base = sb + (OFF_K0 + (wid * 16 + lrow) * PITCH + lcol) * 2;
        #pragma unroll
        for (int kc = 0; kc < 8; ++kc) LDSM4(qf[kc], q_base + kc * 32);
    }
    __syncthreads();  // all Q fragment reads done before K0 is overwritten

    stage(0, 0);
    CPCOMMIT();

    const uint32_t k_base[2] = {sb + (OFF_K0 + lrow * PITCH + lcol) * 2,
                                sb + (OFF_K1 + lrow * PITCH + lcol) * 2};
    const uint32_t v_base[2] = {sb + (OFF_V0 + lrow * PITCH + lcol) * 2,
                                sb + (OFF_V1 + lrow * PITCH + lcol) * 2};

    float oacc[16][4];
    #pragma unroll
    for (int i = 0; i < 16; ++i)
        #pragma unroll
        for (int j = 0; j < 4; ++j) oacc[i][j] = 0.0f;
    float ls[4] = {0.0f, 0.0f, 0.0f, 0.0f};  // row-sum accumulator (via ones-MMA)

    int rg0 = m0 + wid * 16 + qr;
    int rg1 = rg0 + 8;

    int ntiles = mt + 1;
    for (int t = 0; t < ntiles; ++t) {
        int bf = t & 1;
        // Single sync per tile: wait for tile t's data (committed last iter),
        // barrier proves all warps done reading the buffer stage(t+1) overwrites.
        CPWAIT0();
        __syncthreads();
        if (t + 1 < ntiles) stage(t + 1, bf ^ 1);
        CPCOMMIT();

        int n0 = t * 64;
        bool diag = (t == ntiles - 1);

        // ---- GEMM1: S = Q' * K'^T, 16 groups, reg double-buffered LDSM ----
        float sacc[8][4];
        #pragma unroll
        for (int i = 0; i < 8; ++i)
            #pragma unroll
            for (int j = 0; j < 4; ++j) sacc[i][j] = 0.0f;

        {
            uint32_t kfrag[2][8];
            LDSM4(kfrag[0],     k_base[bf] + 0 * 16 * (PITCH * 2));
            LDSM4(kfrag[0] + 4, k_base[bf] + 1 * 16 * (PITCH * 2));
            #pragma unroll
            for (int i = 0; i < 16; ++i) {
                int cur = i & 1, nxt = cur ^ 1;
                if (i < 15) {
                    int kc2 = (i + 1) >> 1, g2 = (i + 1) & 1;
                    LDSM4(kfrag[nxt],     k_base[bf] + (2 * g2)     * 16 * (PITCH * 2) + kc2 * 32);
                    LDSM4(kfrag[nxt] + 4, k_base[bf] + (2 * g2 + 1) * 16 * (PITCH * 2) + kc2 * 32);
                }
                int kc = i >> 1, g = i & 1;
                MMA_F16(sacc[4 * g],     qf[kc][0], qf[kc][1], qf[kc][2], qf[kc][3], kfrag[cur][0], kfrag[cur][2]);
                MMA_F16(sacc[4 * g + 1], qf[kc][0], qf[kc][1], qf[kc][2], qf[kc][3], kfrag[cur][1], kfrag[cur][3]);
                MMA_F16(sacc[4 * g + 2], qf[kc][0], qf[kc][1], qf[kc][2], qf[kc][3], kfrag[cur][4], kfrag[cur][6]);
                MMA_F16(sacc[4 * g + 3], qf[kc][0], qf[kc][1], qf[kc][2], qf[kc][3], kfrag[cur][5], kfrag[cur][7]);
            }
        }

        // ---- softmax: pack ex2-args to half2, one f16x2 ex2 per pair ----
        uint32_t P[8][2];
        #pragma unroll
        for (int j = 0; j < 8; ++j) {
            int cg = n0 + j * 8 + qc;
            float t00 = sacc[j][0];
            float t01 = sacc[j][1];
            float t10 = sacc[j][2];
            float t11 = sacc[j][3];
            if (diag) {
                t00 = (cg     > rg0) ? -1e4f : t00;
                t01 = (cg + 1 > rg0) ? -1e4f : t01;
                t10 = (cg     > rg1) ? -1e4f : t10;
                t11 = (cg + 1 > rg1) ? -1e4f : t11;
            }
            P[j][0] = ex2_f16x2(pack_f16(t00, t01));
            P[j][1] = ex2_f16x2(pack_f16(t10, t11));
        }

        // ---- row sums via ones-MMA first (no LDSM dep; fills LDSM latency) ----
        #pragma unroll
        for (int kt = 0; kt < 4; ++kt)
            MMA_F16(ls, P[2 * kt][0], P[2 * kt][1], P[2 * kt + 1][0], P[2 * kt + 1][1], ONES2, ONES2);

        // ---- GEMM2: O += P * V', 16 groups, reg double-buffered LDSM ----
        {
            uint32_t vfrag[2][8];
            LDSM4T(vfrag[0],     v_base[bf] + 0 * 32);
            LDSM4T(vfrag[0] + 4, v_base[bf] + 1 * 32);
            #pragma unroll
            for (int i = 0; i < 16; ++i) {
                int cur = i & 1, nxt = cur ^ 1;
                if (i < 15) {
                    int kt2 = (i + 1) >> 2, g2 = (i + 1) & 3;
                    LDSM4T(vfrag[nxt],     v_base[bf] + kt2 * 16 * (PITCH * 2) + (2 * g2)     * 32);
                    LDSM4T(vfrag[nxt] + 4, v_base[bf] + kt2 * 16 * (PITCH * 2) + (2 * g2 + 1) * 32);
                }
                int kt = i >> 2, g = i & 3;
                uint32_t a0 = P[2 * kt][0], a1 = P[2 * kt][1];
                uint32_t a2 = P[2 * kt + 1][0], a3 = P[2 * kt + 1][1];
                MMA_F16(oacc[4 * g],     a0, a1, a2, a3, vfrag[cur][0], vfrag[cur][1]);
                MMA_F16(oacc[4 * g + 1], a0, a1, a2, a3, vfrag[cur][2], vfrag[cur][3]);
                MMA_F16(oacc[4 * g + 2], a0, a1, a2, a3, vfrag[cur][4], vfrag[cur][5]);
                MMA_F16(oacc[4 * g + 3], a0, a1, a2, a3, vfrag[cur][6], vfrag[cur][7]);
            }
        }
    }

    // ---- epilogue: ls[0]/ls[2] are full row sums (all lanes in quad agree) ----
    float inv0 = 1.0f / ls[0], inv1 = 1.0f / ls[2];

    float* o0 = out + ((size_t)(b * SS + rg0) * HQN + hq) * DD;
    float* o1 = out + ((size_t)(b * SS + rg1) * HQN + hq) * DD;
    #pragma unroll
    for (int dt = 0; dt < 16; ++dt) {
        int d = dt * 8 + qc;
        *(float2*)(o0 + d) = make_float2(oacc[dt][0] * inv0, oacc[dt][1] * inv0);
        *(float2*)(o1 + d) = make_float2(oacc[dt][2] * inv1, oacc[dt][3] * inv1);
    }
}

extern "C" void kernel_launch(void* const* d_in, const int* in_sizes, int n_in,
                              void* d_out, int out_size) {
    (void)in_sizes; (void)n_in; (void)out_size;
    const float* q = (const float*)d_in[0];
    const float* k = (const float*)d_in[1];
    const float* v = (const float*)d_in[2];
    float* out = (float*)d_out;

    cudaFuncSetAttribute(attn_kernel, cudaFuncAttributeMaxDynamicSharedMemorySize,
                         SMEM_BYTES);

    int prep_rows = BB * SS * HKV;
    dim3 pgrid((prep_rows * 32 + 255) / 256, 2);
    prep_kernel<<<pgrid, 256>>>(k, v);

    attn_kernel<<<(SS / 64) * BB * HQN, 128, SMEM_BYTES>>>(q, out);
}

// round 17
// speedup vs baseline: 1.1001x; 1.0178x over previous
#include <cuda_runtime.h>
#include <cuda_fp16.h>
#include <math.h>
#include <stdint.h>

#define BB 2
#define SS 2048
#define HQN 32
#define HKV 8
#define DD 128
#define SCALING 0.08838834764831845f
#define LOG2E 1.4426950408889634f

// ---------------- device scratch ----------------
__device__ __half g_kg[(size_t)BB * HKV * SS * DD];  // K' [b][h][s][d] (scale folded)
__device__ __half g_vg[(size_t)BB * HKV * SS * DD];  // V' [b][h][s][d] (scale folded)

// ---------------- prep: e4m3 qd (bit-exact) -> fp4 dequant, scale folded ----------------
__device__ __forceinline__ float e4m3_qd(float x) {
    uint32_t u = __float_as_uint(x);
    uint32_t au = u & 0x7FFFFFFFu;
    float ax = __uint_as_float(au);
    uint32_t lsb = (au >> 20) & 1u;
    uint32_t r = au + 0x7FFFFu + lsb;
    float fn = fminf(__uint_as_float(r & 0xFFF00000u), 448.0f);
    float fs = rintf(ax * 512.0f) * (1.0f / 512.0f);
    float q = (ax < 0.015625f) ? fs : fn;
    return copysignf(q, x);
}

__global__ void prep_kernel(const float* __restrict__ ksrc, const float* __restrict__ vsrc) {
    int which = blockIdx.y;
    const float* __restrict__ src = which ? vsrc : ksrc;
    int gw = (blockIdx.x * blockDim.x + threadIdx.x) >> 5;
    if (gw >= BB * SS * HKV) return;
    int lane = threadIdx.x & 31;
    int h = gw % HKV;
    int t = gw / HKV;
    int s = t % SS;
    int b = t / SS;

    const float4* p = (const float4*)(src + ((size_t)(b * SS + s) * HKV + h) * DD);
    float4 xv = p[lane];
    float qq[4];
    qq[0] = e4m3_qd(xv.x); qq[1] = e4m3_qd(xv.y);
    qq[2] = e4m3_qd(xv.z); qq[3] = e4m3_qd(xv.w);

    float am = fmaxf(fmaxf(fabsf(qq[0]), fabsf(qq[1])), fmaxf(fabsf(qq[2]), fabsf(qq[3])));
    #pragma unroll
    for (int o = 16; o >= 1; o >>= 1)
        am = fmaxf(am, __shfl_xor_sync(0xffffffffu, am, o));
    float scale = fmaxf(__fdiv_rn(am, 6.0f), 1e-12f);

    float rr[4];
    #pragma unroll
    for (int u = 0; u < 4; ++u) {
        float xn = __fdiv_rn(qq[u], scale);
        float axn = fabsf(xn);
        float g = axn <= 0.25f ? 0.0f :
                  axn <= 0.75f ? 0.5f :
                  axn <= 1.25f ? 1.0f :
                  axn <= 1.75f ? 1.5f :
                  axn <= 2.5f  ? 2.0f :
                  axn <= 3.5f  ? 3.0f :
                  axn <= 5.0f  ? 4.0f : 6.0f;
        float sg = xn > 0.0f ? 1.0f : (xn < 0.0f ? -1.0f : 0.0f);
        rr[u] = sg * g * scale;
    }

    size_t bh = (size_t)(b * HKV + h);
    __half* dst = (which ? g_vg : g_kg) + (bh * SS + s) * DD + lane * 4;
    dst[0] = __float2half_rn(rr[0]); dst[1] = __float2half_rn(rr[1]);
    dst[2] = __float2half_rn(rr[2]); dst[3] = __float2half_rn(rr[3]);
}

// ---------------- mma.sync helpers ----------------
__device__ __forceinline__ uint32_t smem_u32(const void* p) {
    uint32_t a;
    asm("{ .reg .u64 t; cvta.to.shared.u64 t, %1; cvt.u32.u64 %0, t; }" : "=r"(a) : "l"(p));
    return a;
}

#define MMA_F16(c, a0, a1, a2, a3, b0, b1)                                      \
    asm volatile("mma.sync.aligned.m16n8k16.row.col.f32.f16.f16.f32 "           \
        "{%0,%1,%2,%3}, {%4,%5,%6,%7}, {%8,%9}, {%0,%1,%2,%3};"                 \
        : "+f"((c)[0]), "+f"((c)[1]), "+f"((c)[2]), "+f"((c)[3])                \
        : "r"(a0), "r"(a1), "r"(a2), "r"(a3), "r"(b0), "r"(b1))

// fp16-accumulate variant: D/C are 2 packed f16x2 regs {c0c1, c2c3}
#define MMA_F16H(c, a0, a1, a2, a3, b0, b1)                                     \
    asm volatile("mma.sync.aligned.m16n8k16.row.col.f16.f16.f16.f16 "           \
        "{%0,%1}, {%2,%3,%4,%5}, {%6,%7}, {%0,%1};"                             \
        : "+r"((c)[0]), "+r"((c)[1])                                            \
        : "r"(a0), "r"(a1), "r"(a2), "r"(a3), "r"(b0), "r"(b1))

#define LDSM4(r, a)                                                             \
    asm volatile("ldmatrix.sync.aligned.m8n8.x4.shared.b16 {%0,%1,%2,%3}, [%4];" \
        : "=r"((r)[0]), "=r"((r)[1]), "=r"((r)[2]), "=r"((r)[3]) : "r"(a))

#define LDSM4T(r, a)                                                            \
    asm volatile("ldmatrix.sync.aligned.m8n8.x4.trans.shared.b16 {%0,%1,%2,%3}, [%4];" \
        : "=r"((r)[0]), "=r"((r)[1]), "=r"((r)[2]), "=r"((r)[3]) : "r"(a))

#define CP16(dst, src) asm volatile("cp.async.cg.shared.global [%0], [%1], 16;" :: "r"(dst), "l"(src))
#define CPCOMMIT()     asm volatile("cp.async.commit_group;" ::: "memory")
#define CPWAIT0()      asm volatile("cp.async.wait_group 0;" ::: "memory")

__device__ __forceinline__ uint32_t pack_f16(float a, float b) {
    __half2 h = __floats2half2_rn(a, b);
    return *reinterpret_cast<uint32_t*>(&h);
}
__device__ __forceinline__ uint32_t ex2_f16x2(uint32_t a) {
    uint32_t r;
    asm("ex2.approx.f16x2 %0, %1;" : "=r"(r) : "r"(a));
    return r;
}

#define ONES2   0x3C003C00u  // half2(1.0, 1.0)
#define NINF_LO 0x0000FC00u  // f16 -inf in low half
#define NINF_HI 0xFC000000u  // f16 -inf in high half

// smem pitch: 136 halfs (272 B) per 128-elem row -> conflict-free ldmatrix.
#define PITCH 136
#define OFF_K0 0
#define OFF_K1 (64 * PITCH)
#define OFF_V0 (2 * 64 * PITCH)
#define OFF_V1 (3 * 64 * PITCH)
#define SMEM_HALFS (4 * 64 * PITCH)
#define SMEM_BYTES (SMEM_HALFS * 2)          // ~69.6 KB -> 3 CTAs/SM

// ---------------- flash attention (fp16-acc GEMM1, single-sync pipeline) ----------------
__global__ __launch_bounds__(128, 3)
void attn_kernel(const float* __restrict__ q, float* __restrict__ out) {
    extern __shared__ __align__(16) __half smem[];

    const uint32_t sb = smem_u32(smem);
    int tid = threadIdx.x;
    int wid = tid >> 5;
    int lane = tid & 31;
    int lrow = lane & 15;
    int lcol = (lane >> 4) << 3;
    int qr = lane >> 2;
    int qc = (lane & 3) << 1;

    int idx = blockIdx.x;
    int bh = idx & 63;
    int mt = 31 - (idx >> 6);      // heavy tiles first
    int b = bh >> 5, hq = bh & 31, hkv = hq >> 2;
    int m0 = mt * 64;

    const __half* kgb = g_kg + (size_t)(b * HKV + hkv) * SS * DD;
    const __half* vgb = g_vg + (size_t)(b * HKV + hkv) * SS * DD;

    int srow = tid >> 4, sch = tid & 15;     // staging: 8 rows per pass
    const uint32_t koff[2] = {sb + (OFF_K0 + srow * PITCH + sch * 8) * 2,
                              sb + (OFF_K1 + srow * PITCH + sch * 8) * 2};
    const uint32_t voff[2] = {sb + (OFF_V0 + srow * PITCH + sch * 8) * 2,
                              sb + (OFF_V1 + srow * PITCH + sch * 8) * 2};

    auto stage = [&](int t, int bf) {
        int n0 = t * 64;
        const __half* kp = kgb + (size_t)(n0 + srow) * DD + sch * 8;
        const __half* vp = vgb + (size_t)(n0 + srow) * DD + sch * 8;
        #pragma unroll
        for (int j = 0; j < 8; ++j) {
            CP16(koff[bf] + j * 8 * PITCH * 2, kp + (size_t)j * 8 * DD);
            CP16(voff[bf] + j * 8 * PITCH * 2, vp + (size_t)j * 8 * DD);
        }
    };

    // ---- stage Q (pre-scaled by SCALING*LOG2E) through K0, hoist, free ----
    {
        int c = tid & 31, r4 = tid >> 5;
        const float* qb = q + ((size_t)(b * SS + m0) * HQN + hq) * DD;
        const float qs = SCALING * LOG2E;
        #pragma unroll
        for (int j = 0; j < 16; ++j) {
            int m = j * 4 + r4;
            float4 v = *(const float4*)(qb + (size_t)m * HQN * DD + c * 4);
            uint32_t* ph = (uint32_t*)(smem + OFF_K0 + m * PITCH + c * 4);
            ph[0] = pack_f16(v.x * qs, v.y * qs);
            ph[1] = pack_f16(v.z * qs, v.w * qs);
        }
    }
    __syncthreads();
    uint32_t qf[8][4];
    {
        const uint32_t q_base = sb + (OFF_K0 + (wid * 16 + lrow) * PITCH + lcol) * 2;
        #pragma unroll
        for (int kc = 0; kc < 8; ++kc) LDSM4(qf[kc], q_base + kc * 32);
    }
    __syncthreads();  // all Q fragment reads done before K0 is overwritten

    stage(0, 0);
    CPCOMMIT();

    const uint32_t k_base[2] = {sb + (OFF_K0 + lrow * PITCH + lcol) * 2,
                                sb + (OFF_K1 + lrow * PITCH + lcol) * 2};
    const uint32_t v_base[2] = {sb + (OFF_V0 + lrow * PITCH + lcol) * 2,
                                sb + (OFF_V1 + lrow * PITCH + lcol) * 2};

    float oacc[16][4];
    #pragma unroll
    for (int i = 0; i < 16; ++i)
        #pragma unroll
        for (int j = 0; j < 4; ++j) oacc[i][j] = 0.0f;
    float ls[4] = {0.0f, 0.0f, 0.0f, 0.0f};  // row-sum accumulator (via ones-MMA)

    int rg0 = m0 + wid * 16 + qr;
    int rg1 = rg0 + 8;

    int ntiles = mt + 1;
    for (int t = 0; t < ntiles; ++t) {
        int bf = t & 1;
        // Single sync per tile: wait for tile t's data (committed last iter),
        // barrier proves all warps done reading the buffer stage(t+1) overwrites.
        CPWAIT0();
        __syncthreads();
        if (t + 1 < ntiles) stage(t + 1, bf ^ 1);
        CPCOMMIT();

        int n0 = t * 64;
        bool diag = (t == ntiles - 1);

        // ---- GEMM1 (fp16 accum): S = Q' * K'^T; D-frag IS the ex2 argument ----
        uint32_t sacc[8][2];
        #pragma unroll
        for (int i = 0; i < 8; ++i) { sacc[i][0] = 0; sacc[i][1] = 0; }

        {
            uint32_t kfrag[2][8];
            LDSM4(kfrag[0],     k_base[bf] + 0 * 16 * (PITCH * 2));
            LDSM4(kfrag[0] + 4, k_base[bf] + 1 * 16 * (PITCH * 2));
            #pragma unroll
            for (int i = 0; i < 16; ++i) {
                int cur = i & 1, nxt = cur ^ 1;
                if (i < 15) {
                    int kc2 = (i + 1) >> 1, g2 = (i + 1) & 1;
                    LDSM4(kfrag[nxt],     k_base[bf] + (2 * g2)     * 16 * (PITCH * 2) + kc2 * 32);
                    LDSM4(kfrag[nxt] + 4, k_base[bf] + (2 * g2 + 1) * 16 * (PITCH * 2) + kc2 * 32);
                }
                int kc = i >> 1, g = i & 1;
                MMA_F16H(sacc[4 * g],     qf[kc][0], qf[kc][1], qf[kc][2], qf[kc][3], kfrag[cur][0], kfrag[cur][2]);
                MMA_F16H(sacc[4 * g + 1], qf[kc][0], qf[kc][1], qf[kc][2], qf[kc][3], kfrag[cur][1], kfrag[cur][3]);
                MMA_F16H(sacc[4 * g + 2], qf[kc][0], qf[kc][1], qf[kc][2], qf[kc][3], kfrag[cur][4], kfrag[cur][6]);
                MMA_F16H(sacc[4 * g + 3], qf[kc][0], qf[kc][1], qf[kc][2], qf[kc][3], kfrag[cur][5], kfrag[cur][7]);
            }
        }

        // ---- softmax: splice f16 -inf for masked cols, then ex2.f16x2 ----
        uint32_t P[8][2];
        #pragma unroll
        for (int j = 0; j < 8; ++j) {
            uint32_t lo = sacc[j][0];   // {col qc, col qc+1} row rg0
            uint32_t hi = sacc[j][1];   // {col qc, col qc+1} row rg1
            if (diag) {
                int cg = n0 + j * 8 + qc;
                if (cg     > rg0) lo = (lo & 0xFFFF0000u) | NINF_LO;
                if (cg + 1 > rg0) lo = (lo & 0x0000FFFFu) | NINF_HI;
                if (cg     > rg1) hi = (hi & 0xFFFF0000u) | NINF_LO;
                if (cg + 1 > rg1) hi = (hi & 0x0000FFFFu) | NINF_HI;
            }
            P[j][0] = ex2_f16x2(lo);
            P[j][1] = ex2_f16x2(hi);
        }

        // ---- row sums via ones-MMA first (no LDSM dep; fills LDSM latency) ----
        #pragma unroll
        for (int kt = 0; kt < 4; ++kt)
            MMA_F16(ls, P[2 * kt][0], P[2 * kt][1], P[2 * kt + 1][0], P[2 * kt + 1][1], ONES2, ONES2);

        // ---- GEMM2: O += P * V', 16 groups, reg double-buffered LDSM ----
        {
            uint32_t vfrag[2][8];
            LDSM4T(vfrag[0],     v_base[bf] + 0 * 32);
            LDSM4T(vfrag[0] + 4, v_base[bf] + 1 * 32);
            #pragma unroll
            for (int i = 0; i < 16; ++i) {
                int cur = i & 1, nxt = cur ^ 1;
                if (i < 15) {
                    int kt2 = (i + 1) >> 2, g2 = (i + 1) & 3;
                    LDSM4T(vfrag[nxt],     v_base[bf] + kt2 * 16 * (PITCH * 2) + (2 * g2)     * 32);
                    LDSM4T(vfrag[nxt] + 4, v_base[bf] + kt2 * 16 * (PITCH * 2) + (2 * g2 + 1) * 32);
                }
                int kt = i >> 2, g = i & 3;
                uint32_t a0 = P[2 * kt][0], a1 = P[2 * kt][1];
                uint32_t a2 = P[2 * kt + 1][0], a3 = P[2 * kt + 1][1];
                MMA_F16(oacc[4 * g],     a0, a1, a2, a3, vfrag[cur][0], vfrag[cur][1]);
                MMA_F16(oacc[4 * g + 1], a0, a1, a2, a3, vfrag[cur][2], vfrag[cur][3]);
                MMA_F16(oacc[4 * g + 2], a0, a1, a2, a3, vfrag[cur][4], vfrag[cur][5]);
                MMA_F16(oacc[4 * g + 3], a0, a1, a2, a3, vfrag[cur][6], vfrag[cur][7]);
            }
        }
    }

    // ---- epilogue: ls[0]/ls[2] are full row sums (all lanes in quad agree) ----
    float inv0 = 1.0f / ls[0], inv1 = 1.0f / ls[2];

    float* o0 = out + ((size_t)(b * SS + rg0) * HQN + hq) * DD;
    float* o1 = out + ((size_t)(b * SS + rg1) * HQN + hq) * DD;
    #pragma unroll
    for (int dt = 0; dt < 16; ++dt) {
        int d = dt * 8 + qc;
        *(float2*)(o0 + d) = make_float2(oacc[dt][0] * inv0, oacc[dt][1] * inv0);
        *(float2*)(o1 + d) = make_float2(oacc[dt][2] * inv1, oacc[dt][3] * inv1);
    }
}

extern "C" void kernel_launch(void* const* d_in, const int* in_sizes, int n_in,
                              void* d_out, int out_size) {
    (void)in_sizes; (void)n_in; (void)out_size;
    const float* q = (const float*)d_in[0];
    const float* k = (const float*)d_in[1];
    const float* v = (const float*)d_in[2];
    float* out = (float*)d_out;

    cudaFuncSetAttribute(attn_kernel, cudaFuncAttributeMaxDynamicSharedMemorySize,
                         SMEM_BYTES);

    int prep_rows = BB * SS * HKV;
    dim3 pgrid((prep_rows * 32 + 255) / 256, 2);
    prep_kernel<<<pgrid, 256>>>(k, v);

    attn_kernel<<<(SS / 64) * BB * HQN, 128, SMEM_BYTES>>>(q, out);
}